// round 9
// baseline (speedup 1.0000x reference)
#include <cuda_runtime.h>

// Row-wise cosine similarity * 0.5 over [B=16384, D=4096] fp32.
// v5b (R7/R8 were container-level infra failures; experiment still
// unmeasured): CTA (256 thr) processes 8 rows in a loop with an 8-deep
// front-batched float4 load burst per row. NO barrier inside the loop:
// the per-row cross-warp combine is deferred (lane0 -> smem partials),
// so the next row's independent load burst can issue underneath the
// current row's shuffle chain. One __syncthreads per CTA, then warp w
// combines row w's 8 partials. Grid = 2048 long-lived CTAs (~1.7 waves).

#define D_DIM 4096
#define THREADS 256
#define ROWS_PER_CTA 8
#define NWARPS 8

__global__ __launch_bounds__(THREADS) void dis_cos_v5b_kernel(
    const float* __restrict__ x1,
    const float* __restrict__ x2,
    float* __restrict__ out)
{
    const int tid = threadIdx.x;
    const int wid = tid >> 5;
    const int lid = tid & 31;
    const int row_base = blockIdx.x * ROWS_PER_CTA;

    // Flattened: [sum_kind * ROWS_PER_CTA * NWARPS]
    __shared__ float s_part[3 * ROWS_PER_CTA * NWARPS];

#pragma unroll
    for (int r = 0; r < ROWS_PER_CTA; ++r) {
        const size_t base = (size_t)(row_base + r) * D_DIM;
        const float4* r1 = reinterpret_cast<const float4*>(x1 + base);
        const float4* r2 = reinterpret_cast<const float4*>(x2 + base);

        float dot = 0.f, sx = 0.f, sy = 0.f;

        float4 a0 = r1[tid + 0 * THREADS];
        float4 a1 = r1[tid + 1 * THREADS];
        float4 a2 = r1[tid + 2 * THREADS];
        float4 a3 = r1[tid + 3 * THREADS];
        float4 b0 = r2[tid + 0 * THREADS];
        float4 b1 = r2[tid + 1 * THREADS];
        float4 b2 = r2[tid + 2 * THREADS];
        float4 b3 = r2[tid + 3 * THREADS];

        dot = fmaf(a0.x, b0.x, dot); dot = fmaf(a0.y, b0.y, dot);
        dot = fmaf(a0.z, b0.z, dot); dot = fmaf(a0.w, b0.w, dot);
        dot = fmaf(a1.x, b1.x, dot); dot = fmaf(a1.y, b1.y, dot);
        dot = fmaf(a1.z, b1.z, dot); dot = fmaf(a1.w, b1.w, dot);
        dot = fmaf(a2.x, b2.x, dot); dot = fmaf(a2.y, b2.y, dot);
        dot = fmaf(a2.z, b2.z, dot); dot = fmaf(a2.w, b2.w, dot);
        dot = fmaf(a3.x, b3.x, dot); dot = fmaf(a3.y, b3.y, dot);
        dot = fmaf(a3.z, b3.z, dot); dot = fmaf(a3.w, b3.w, dot);

        sx = fmaf(a0.x, a0.x, sx); sx = fmaf(a0.y, a0.y, sx);
        sx = fmaf(a0.z, a0.z, sx); sx = fmaf(a0.w, a0.w, sx);
        sx = fmaf(a1.x, a1.x, sx); sx = fmaf(a1.y, a1.y, sx);
        sx = fmaf(a1.z, a1.z, sx); sx = fmaf(a1.w, a1.w, sx);
        sx = fmaf(a2.x, a2.x, sx); sx = fmaf(a2.y, a2.y, sx);
        sx = fmaf(a2.z, a2.z, sx); sx = fmaf(a2.w, a2.w, sx);
        sx = fmaf(a3.x, a3.x, sx); sx = fmaf(a3.y, a3.y, sx);
        sx = fmaf(a3.z, a3.z, sx); sx = fmaf(a3.w, a3.w, sx);

        sy = fmaf(b0.x, b0.x, sy); sy = fmaf(b0.y, b0.y, sy);
        sy = fmaf(b0.z, b0.z, sy); sy = fmaf(b0.w, b0.w, sy);
        sy = fmaf(b1.x, b1.x, sy); sy = fmaf(b1.y, b1.y, sy);
        sy = fmaf(b1.z, b1.z, sy); sy = fmaf(b1.w, b1.w, sy);
        sy = fmaf(b2.x, b2.x, sy); sy = fmaf(b2.y, b2.y, sy);
        sy = fmaf(b2.z, b2.z, sy); sy = fmaf(b2.w, b2.w, sy);
        sy = fmaf(b3.x, b3.x, sy); sy = fmaf(b3.y, b3.y, sy);
        sy = fmaf(b3.z, b3.z, sy); sy = fmaf(b3.w, b3.w, sy);

        // Warp-level reduce; next row's loads are independent and can be
        // issued underneath this chain (no barrier in the way).
#pragma unroll
        for (int off = 16; off > 0; off >>= 1) {
            dot += __shfl_down_sync(0xFFFFFFFFu, dot, off);
            sx  += __shfl_down_sync(0xFFFFFFFFu, sx,  off);
            sy  += __shfl_down_sync(0xFFFFFFFFu, sy,  off);
        }
        if (lid == 0) {
            s_part[(0 * ROWS_PER_CTA + r) * NWARPS + wid] = dot;
            s_part[(1 * ROWS_PER_CTA + r) * NWARPS + wid] = sx;
            s_part[(2 * ROWS_PER_CTA + r) * NWARPS + wid] = sy;
        }
    }

    __syncthreads();

    // Warp w combines row w: 8 per-warp partials per sum.
    float dot = (lid < NWARPS) ? s_part[(0 * ROWS_PER_CTA + wid) * NWARPS + lid] : 0.f;
    float sx  = (lid < NWARPS) ? s_part[(1 * ROWS_PER_CTA + wid) * NWARPS + lid] : 0.f;
    float sy  = (lid < NWARPS) ? s_part[(2 * ROWS_PER_CTA + wid) * NWARPS + lid] : 0.f;
#pragma unroll
    for (int off = 4; off > 0; off >>= 1) {
        dot += __shfl_down_sync(0xFFFFFFFFu, dot, off);
        sx  += __shfl_down_sync(0xFFFFFFFFu, sx,  off);
        sy  += __shfl_down_sync(0xFFFFFFFFu, sy,  off);
    }
    if (lid == 0) {
        out[row_base + wid] = 0.5f * dot * rsqrtf(sx * sy);
    }
}

extern "C" void kernel_launch(void* const* d_in, const int* in_sizes, int n_in,
                              void* d_out, int out_size)
{
    const float* x1 = (const float*)d_in[0];
    const float* x2 = (const float*)d_in[1];
    float* out = (float*)d_out;
    const int B = out_size;  // 16384 rows
    dis_cos_v5b_kernel<<<B / ROWS_PER_CTA, THREADS>>>(x1, x2, out);
}

// round 10
// speedup vs baseline: 1.0587x; 1.0587x over previous
#include <cuda_runtime.h>

// Row-wise cosine similarity * 0.5 over [B=16384, D=4096] fp32.
// v6: two independent v1-style row units fused in one 512-thread CTA.
// Warps 0-7 process row 2*b, warps 8-15 process row 2*b+1. The halves
// share NOTHING: separate smem slices and separate named barriers
// (bar.sync 1/2, 256 threads each), so each half is byte-identical in
// behavior to a v1 CTA. Grid 8192 -> half the wave transitions.

#define D_DIM 4096
#define THREADS 512
#define HALF 256

__global__ __launch_bounds__(THREADS) void dis_cos_v6_kernel(
    const float* __restrict__ x1,
    const float* __restrict__ x2,
    float* __restrict__ out)
{
    const int tid   = threadIdx.x;
    const int half  = tid >> 8;          // 0 or 1
    const int htid  = tid & (HALF - 1);  // 0..255 within half
    const int wid   = htid >> 5;         // 0..7 within half
    const int lid   = tid & 31;
    const int row   = blockIdx.x * 2 + half;

    const float4* r1 = reinterpret_cast<const float4*>(x1 + (size_t)row * D_DIM);
    const float4* r2 = reinterpret_cast<const float4*>(x2 + (size_t)row * D_DIM);

    float dot = 0.f, sx = 0.f, sy = 0.f;

    // v1's 8-deep front-batched burst (4 float4 per input per thread)
    float4 a[4], b[4];
#pragma unroll
    for (int i = 0; i < 4; ++i) {
        a[i] = r1[htid + i * HALF];
        b[i] = r2[htid + i * HALF];
    }
#pragma unroll
    for (int i = 0; i < 4; ++i) {
        dot = fmaf(a[i].x, b[i].x, dot);
        dot = fmaf(a[i].y, b[i].y, dot);
        dot = fmaf(a[i].z, b[i].z, dot);
        dot = fmaf(a[i].w, b[i].w, dot);
        sx  = fmaf(a[i].x, a[i].x, sx);
        sx  = fmaf(a[i].y, a[i].y, sx);
        sx  = fmaf(a[i].z, a[i].z, sx);
        sx  = fmaf(a[i].w, a[i].w, sx);
        sy  = fmaf(b[i].x, b[i].x, sy);
        sy  = fmaf(b[i].y, b[i].y, sy);
        sy  = fmaf(b[i].z, b[i].z, sy);
        sy  = fmaf(b[i].w, b[i].w, sy);
    }

    // Warp reduce
#pragma unroll
    for (int off = 16; off > 0; off >>= 1) {
        dot += __shfl_down_sync(0xFFFFFFFFu, dot, off);
        sx  += __shfl_down_sync(0xFFFFFFFFu, sx,  off);
        sy  += __shfl_down_sync(0xFFFFFFFFu, sy,  off);
    }

    // Per-half cross-warp stage: separate smem slice + named barrier
    __shared__ float s[2][3][8];
    if (lid == 0) {
        s[half][0][wid] = dot;
        s[half][1][wid] = sx;
        s[half][2][wid] = sy;
    }
    // Named barrier per half (ids 1 and 2), 256 threads each:
    asm volatile("bar.sync %0, %1;" :: "r"(half + 1), "r"(HALF) : "memory");

    if (wid == 0) {
        dot = (lid < 8) ? s[half][0][lid] : 0.f;
        sx  = (lid < 8) ? s[half][1][lid] : 0.f;
        sy  = (lid < 8) ? s[half][2][lid] : 0.f;
#pragma unroll
        for (int off = 4; off > 0; off >>= 1) {
            dot += __shfl_down_sync(0xFFFFFFFFu, dot, off);
            sx  += __shfl_down_sync(0xFFFFFFFFu, sx,  off);
            sy  += __shfl_down_sync(0xFFFFFFFFu, sy,  off);
        }
        if (lid == 0) {
            out[row] = 0.5f * dot * rsqrtf(sx * sy);
        }
    }
}

extern "C" void kernel_launch(void* const* d_in, const int* in_sizes, int n_in,
                              void* d_out, int out_size)
{
    const float* x1 = (const float*)d_in[0];
    const float* x2 = (const float*)d_in[1];
    float* out = (float*)d_out;
    const int B = out_size;  // 16384 rows
    dis_cos_v6_kernel<<<B / 2, THREADS>>>(x1, x2, out);
}